// round 7
// baseline (speedup 1.0000x reference)
#include <cuda_runtime.h>
#include <cstdint>
#include <cfloat>

// Problem constants
#define B_SZ   4
#define S_LEN  1024
#define NTOK   16
#define DMODEL 512
#define NH     8
#define HDIM   64
#define M_ROWS (B_SZ * S_LEN * NTOK)   // 65536
#define QKV_COLS (3 * NH * HDIM)       // 1536

// Scratch (allocation-free rule: __device__ globals)
__device__ float g_qkv[(size_t)M_ROWS * QKV_COLS];   // 402 MB
__device__ float g_ctx[(size_t)M_ROWS * DMODEL];     // 128 MB

// ---------------------------------------------------------------------------
// K1/K3: classic 128x128x16 fp32 SGEMM, 256 threads, 8x8 per thread,
// float4 global loads, split 4+4 register tiles for conflict-free LDS.128.
// Dims are guaranteed multiples of tile sizes for this problem (no bounds).
// ---------------------------------------------------------------------------
__global__ __launch_bounds__(256) void sgemm128(
    const float* __restrict__ A, const float* __restrict__ B,
    float* __restrict__ C, int M, int N, int K)
{
    constexpr int BM = 128, BN = 128, BK = 16;
    __shared__ float As[BK][BM];
    __shared__ float Bs[BK][BN];

    const int tid  = threadIdx.x;
    const int tx   = tid & 15;
    const int ty   = tid >> 4;
    const int row0 = blockIdx.y * BM;
    const int col0 = blockIdx.x * BN;

    // global->smem load assignments
    const int a_r = tid >> 2;          // 0..63 (two passes: +0, +64)
    const int a_c = (tid & 3) << 2;    // 0,4,8,12
    const int b_r = tid >> 5;          // 0..7  (two passes: +0, +8)
    const int b_c = (tid & 31) << 2;   // 0..124

    const float* Ag = A + (size_t)row0 * K;
    const float* Bg = B + col0;

    float acc[8][8];
#pragma unroll
    for (int i = 0; i < 8; i++)
#pragma unroll
        for (int j = 0; j < 8; j++) acc[i][j] = 0.f;

    for (int k0 = 0; k0 < K; k0 += BK) {
#pragma unroll
        for (int i = 0; i < 2; i++) {
            int r = a_r + i * 64;
            float4 v = *reinterpret_cast<const float4*>(Ag + (size_t)r * K + k0 + a_c);
            As[a_c + 0][r] = v.x; As[a_c + 1][r] = v.y;
            As[a_c + 2][r] = v.z; As[a_c + 3][r] = v.w;
        }
#pragma unroll
        for (int i = 0; i < 2; i++) {
            int r = b_r + i * 8;
            *reinterpret_cast<float4*>(&Bs[r][b_c]) =
                *reinterpret_cast<const float4*>(Bg + (size_t)(k0 + r) * N + b_c);
        }
        __syncthreads();

#pragma unroll
        for (int kk = 0; kk < BK; kk++) {
            float ra[8], rb[8];
            *reinterpret_cast<float4*>(&ra[0]) = *reinterpret_cast<const float4*>(&As[kk][ty * 4]);
            *reinterpret_cast<float4*>(&ra[4]) = *reinterpret_cast<const float4*>(&As[kk][64 + ty * 4]);
            *reinterpret_cast<float4*>(&rb[0]) = *reinterpret_cast<const float4*>(&Bs[kk][tx * 4]);
            *reinterpret_cast<float4*>(&rb[4]) = *reinterpret_cast<const float4*>(&Bs[kk][64 + tx * 4]);
#pragma unroll
            for (int i = 0; i < 8; i++)
#pragma unroll
                for (int j = 0; j < 8; j++)
                    acc[i][j] = fmaf(ra[i], rb[j], acc[i][j]);
        }
        __syncthreads();
    }

#pragma unroll
    for (int ig = 0; ig < 2; ig++)
#pragma unroll
        for (int i = 0; i < 4; i++) {
            int r = row0 + ig * 64 + ty * 4 + i;
#pragma unroll
            for (int jg = 0; jg < 2; jg++) {
                int c = col0 + jg * 64 + tx * 4;
                float4 v = make_float4(acc[ig * 4 + i][jg * 4 + 0], acc[ig * 4 + i][jg * 4 + 1],
                                       acc[ig * 4 + i][jg * 4 + 2], acc[ig * 4 + i][jg * 4 + 3]);
                *reinterpret_cast<float4*>(C + (size_t)r * N + c) = v;
            }
        }
}

// ---------------------------------------------------------------------------
// K2: fused rotary + scale + sim + bias + mask + softmax + AV.
// One block per (b, s, h): 256 threads, thread t -> (n = t/16, dg = t%16).
// For focus batches, attention is exactly identity (one-hot softmax), so
// output = V bitwise; just copy.
// ---------------------------------------------------------------------------
__global__ __launch_bounds__(256) void attn_kernel(
    const float* __restrict__ pos_bias,
    const unsigned char* __restrict__ fmask)
{
    const int bs = blockIdx.x >> 3;     // b*S + s
    const int h  = blockIdx.x & 7;
    const int b  = bs / S_LEN;
    const int t  = threadIdx.x;
    const int n  = t >> 4;
    const int dg = t & 15;
    const int d  = dg << 2;

    __shared__ float qs[16][68];
    __shared__ float ks[16][68];
    __shared__ float vs[16][68];
    __shared__ float sim[16][17];

    // --- robust focus_present_mask read (bool may be u8 / i32 / f32) ---
    const uint32_t* fw = reinterpret_cast<const uint32_t*>(fmask);
    uint32_t w0 = fw[0], w1 = fw[1], w2 = fw[2], w3 = fw[3];
    bool is_f32 = ((w0 == 0u || w0 == 0x3F800000u) && (w1 == 0u || w1 == 0x3F800000u) &&
                   (w2 == 0u || w2 == 0x3F800000u) && (w3 == 0u || w3 == 0x3F800000u));
    bool is_i32 = ((w0 <= 1u) && (w1 <= 1u) && (w2 <= 1u) && (w3 <= 1u));
    bool focus;
    if (is_f32 || is_i32) {
        uint32_t wb = (b == 0) ? w0 : (b == 1) ? w1 : (b == 2) ? w2 : w3;
        focus = (wb != 0u);
    } else {
        focus = (fmask[b] != 0);
    }

    const int m = bs * NTOK + n;
    const float* row = g_qkv + (size_t)m * QKV_COLS + h * HDIM + d;
    float4 q4 = *reinterpret_cast<const float4*>(row);
    float4 k4 = *reinterpret_cast<const float4*>(row + 512);
    float4 v4 = *reinterpret_cast<const float4*>(row + 1024);

    float* ctx_out = g_ctx + (size_t)m * DMODEL + h * HDIM + d;

    if (focus) {                       // exact identity attention -> out = v
        *reinterpret_cast<float4*>(ctx_out) = v4;
        return;
    }

    // rotary: pairs (d,d+1) angle p0=d/2, (d+2,d+3) angle p1=d/2+1
    const float L2T = 0.41524101186092029f;   // log2(10000)/32
    float a0 = (float)n * exp2f(-(float)(d >> 1) * L2T);
    float a1 = (float)n * exp2f(-(float)((d >> 1) + 1) * L2T);
    float c0, s0, c1, s1;
    sincosf(a0, &s0, &c0);
    sincosf(a1, &s1, &c1);

    q4.x *= 0.125f; q4.y *= 0.125f; q4.z *= 0.125f; q4.w *= 0.125f;  // hd^-0.5

    float qx = q4.x * c0 - q4.y * s0, qy = q4.y * c0 + q4.x * s0;
    float qz = q4.z * c1 - q4.w * s1, qw = q4.w * c1 + q4.z * s1;
    float kx = k4.x * c0 - k4.y * s0, ky = k4.y * c0 + k4.x * s0;
    float kz = k4.z * c1 - k4.w * s1, kw = k4.w * c1 + k4.z * s1;

    *reinterpret_cast<float4*>(&qs[n][d]) = make_float4(qx, qy, qz, qw);
    *reinterpret_cast<float4*>(&ks[n][d]) = make_float4(kx, ky, kz, kw);
    *reinterpret_cast<float4*>(&vs[n][d]) = v4;
    __syncthreads();

    // sim[i][j] = q_i . k_j + pos_bias[h,i,j]  (thread (n,dg) -> (i=n, j=dg))
    {
        const float4* qr = reinterpret_cast<const float4*>(&qs[n][0]);
        const float4* kr = reinterpret_cast<const float4*>(&ks[dg][0]);
        float acc = 0.f;
#pragma unroll
        for (int dd = 0; dd < 16; dd++) {
            float4 a = qr[dd], bb = kr[dd];
            acc += a.x * bb.x + a.y * bb.y + a.z * bb.z + a.w * bb.w;
        }
        sim[n][dg] = acc + pos_bias[(h * 16 + n) * 16 + dg];
    }
    __syncthreads();

    // softmax per row (16 rows, one thread each)
    if (t < 16) {
        float mx = -FLT_MAX;
#pragma unroll
        for (int j = 0; j < 16; j++) mx = fmaxf(mx, sim[t][j]);
        float e[16], sum = 0.f;
#pragma unroll
        for (int j = 0; j < 16; j++) { e[j] = expf(sim[t][j] - mx); sum += e[j]; }
#pragma unroll
        for (int j = 0; j < 16; j++) sim[t][j] = e[j] / sum;
    }
    __syncthreads();

    // out[n][d..d+3] = sum_j attn[n][j] * v[j][d..d+3]
    float4 o = make_float4(0.f, 0.f, 0.f, 0.f);
#pragma unroll
    for (int j = 0; j < 16; j++) {
        float a = sim[n][j];
        float4 vv = *reinterpret_cast<const float4*>(&vs[j][d]);
        o.x = fmaf(a, vv.x, o.x); o.y = fmaf(a, vv.y, o.y);
        o.z = fmaf(a, vv.z, o.z); o.w = fmaf(a, vv.w, o.w);
    }
    *reinterpret_cast<float4*>(ctx_out) = o;
}

// ---------------------------------------------------------------------------
extern "C" void kernel_launch(void* const* d_in, const int* in_sizes, int n_in,
                              void* d_out, int out_size)
{
    const float* x     = (const float*)d_in[0];   // (4,1024,16,512)
    const float* pbias = (const float*)d_in[1];   // (8,16,16)
    const float* Wqkv  = (const float*)d_in[2];   // (512,1536)
    const float* Wout  = (const float*)d_in[3];   // (512,512)
    const unsigned char* fmask = (const unsigned char*)d_in[4];
    float* out = (float*)d_out;                   // (4,1024,16,512)

    float *qkv = nullptr, *ctx = nullptr;
    cudaGetSymbolAddress((void**)&qkv, g_qkv);
    cudaGetSymbolAddress((void**)&ctx, g_ctx);

    dim3 blk(256);

    // K1: qkv = x @ W_qkv   (65536 x 1536, K=512)
    dim3 g1(QKV_COLS / 128, M_ROWS / 128);
    sgemm128<<<g1, blk>>>(x, Wqkv, qkv, M_ROWS, QKV_COLS, DMODEL);

    // K2: fused rotary/attention -> g_ctx (65536 x 512)
    attn_kernel<<<B_SZ * S_LEN * NH, blk>>>(pbias, fmask);

    // K3: out = ctx @ W_out  (65536 x 512, K=512)
    dim3 g3(DMODEL / 128, M_ROWS / 128);
    sgemm128<<<g3, blk>>>(ctx, Wout, out, M_ROWS, DMODEL, DMODEL);
}

// round 8
// speedup vs baseline: 1.0000x; 1.0000x over previous
#include <cuda_runtime.h>
#include <cstdint>
#include <cfloat>

// Problem constants
#define B_SZ   4
#define S_LEN  1024
#define NTOK   16
#define DMODEL 512
#define NH     8
#define HDIM   64
#define M_ROWS (B_SZ * S_LEN * NTOK)   // 65536
#define QKV_COLS (3 * NH * HDIM)       // 1536

// Scratch (allocation-free rule: __device__ globals)
__device__ float g_qkv[(size_t)M_ROWS * QKV_COLS];   // 402 MB
__device__ float g_ctx[(size_t)M_ROWS * DMODEL];     // 128 MB

// ---------------------------------------------------------------------------
// K1/K3: classic 128x128x16 fp32 SGEMM, 256 threads, 8x8 per thread,
// float4 global loads, split 4+4 register tiles for conflict-free LDS.128.
// Dims are guaranteed multiples of tile sizes for this problem (no bounds).
// ---------------------------------------------------------------------------
__global__ __launch_bounds__(256) void sgemm128(
    const float* __restrict__ A, const float* __restrict__ B,
    float* __restrict__ C, int M, int N, int K)
{
    constexpr int BM = 128, BN = 128, BK = 16;
    __shared__ float As[BK][BM];
    __shared__ float Bs[BK][BN];

    const int tid  = threadIdx.x;
    const int tx   = tid & 15;
    const int ty   = tid >> 4;
    const int row0 = blockIdx.y * BM;
    const int col0 = blockIdx.x * BN;

    // global->smem load assignments
    const int a_r = tid >> 2;          // 0..63 (two passes: +0, +64)
    const int a_c = (tid & 3) << 2;    // 0,4,8,12
    const int b_r = tid >> 5;          // 0..7  (two passes: +0, +8)
    const int b_c = (tid & 31) << 2;   // 0..124

    const float* Ag = A + (size_t)row0 * K;
    const float* Bg = B + col0;

    float acc[8][8];
#pragma unroll
    for (int i = 0; i < 8; i++)
#pragma unroll
        for (int j = 0; j < 8; j++) acc[i][j] = 0.f;

    for (int k0 = 0; k0 < K; k0 += BK) {
#pragma unroll
        for (int i = 0; i < 2; i++) {
            int r = a_r + i * 64;
            float4 v = *reinterpret_cast<const float4*>(Ag + (size_t)r * K + k0 + a_c);
            As[a_c + 0][r] = v.x; As[a_c + 1][r] = v.y;
            As[a_c + 2][r] = v.z; As[a_c + 3][r] = v.w;
        }
#pragma unroll
        for (int i = 0; i < 2; i++) {
            int r = b_r + i * 8;
            *reinterpret_cast<float4*>(&Bs[r][b_c]) =
                *reinterpret_cast<const float4*>(Bg + (size_t)(k0 + r) * N + b_c);
        }
        __syncthreads();

#pragma unroll
        for (int kk = 0; kk < BK; kk++) {
            float ra[8], rb[8];
            *reinterpret_cast<float4*>(&ra[0]) = *reinterpret_cast<const float4*>(&As[kk][ty * 4]);
            *reinterpret_cast<float4*>(&ra[4]) = *reinterpret_cast<const float4*>(&As[kk][64 + ty * 4]);
            *reinterpret_cast<float4*>(&rb[0]) = *reinterpret_cast<const float4*>(&Bs[kk][tx * 4]);
            *reinterpret_cast<float4*>(&rb[4]) = *reinterpret_cast<const float4*>(&Bs[kk][64 + tx * 4]);
#pragma unroll
            for (int i = 0; i < 8; i++)
#pragma unroll
                for (int j = 0; j < 8; j++)
                    acc[i][j] = fmaf(ra[i], rb[j], acc[i][j]);
        }
        __syncthreads();
    }

#pragma unroll
    for (int ig = 0; ig < 2; ig++)
#pragma unroll
        for (int i = 0; i < 4; i++) {
            int r = row0 + ig * 64 + ty * 4 + i;
#pragma unroll
            for (int jg = 0; jg < 2; jg++) {
                int c = col0 + jg * 64 + tx * 4;
                float4 v = make_float4(acc[ig * 4 + i][jg * 4 + 0], acc[ig * 4 + i][jg * 4 + 1],
                                       acc[ig * 4 + i][jg * 4 + 2], acc[ig * 4 + i][jg * 4 + 3]);
                *reinterpret_cast<float4*>(C + (size_t)r * N + c) = v;
            }
        }
}

// ---------------------------------------------------------------------------
// K2: fused rotary + scale + sim + bias + mask + softmax + AV.
// One block per (b, s, h): 256 threads, thread t -> (n = t/16, dg = t%16).
// For focus batches, attention is exactly identity (one-hot softmax), so
// output = V bitwise; just copy.
// ---------------------------------------------------------------------------
__global__ __launch_bounds__(256) void attn_kernel(
    const float* __restrict__ pos_bias,
    const unsigned char* __restrict__ fmask)
{
    const int bs = blockIdx.x >> 3;     // b*S + s
    const int h  = blockIdx.x & 7;
    const int b  = bs / S_LEN;
    const int t  = threadIdx.x;
    const int n  = t >> 4;
    const int dg = t & 15;
    const int d  = dg << 2;

    __shared__ float qs[16][68];
    __shared__ float ks[16][68];
    __shared__ float vs[16][68];
    __shared__ float sim[16][17];

    // --- robust focus_present_mask read (bool may be u8 / i32 / f32) ---
    const uint32_t* fw = reinterpret_cast<const uint32_t*>(fmask);
    uint32_t w0 = fw[0], w1 = fw[1], w2 = fw[2], w3 = fw[3];
    bool is_f32 = ((w0 == 0u || w0 == 0x3F800000u) && (w1 == 0u || w1 == 0x3F800000u) &&
                   (w2 == 0u || w2 == 0x3F800000u) && (w3 == 0u || w3 == 0x3F800000u));
    bool is_i32 = ((w0 <= 1u) && (w1 <= 1u) && (w2 <= 1u) && (w3 <= 1u));
    bool focus;
    if (is_f32 || is_i32) {
        uint32_t wb = (b == 0) ? w0 : (b == 1) ? w1 : (b == 2) ? w2 : w3;
        focus = (wb != 0u);
    } else {
        focus = (fmask[b] != 0);
    }

    const int m = bs * NTOK + n;
    const float* row = g_qkv + (size_t)m * QKV_COLS + h * HDIM + d;
    float4 q4 = *reinterpret_cast<const float4*>(row);
    float4 k4 = *reinterpret_cast<const float4*>(row + 512);
    float4 v4 = *reinterpret_cast<const float4*>(row + 1024);

    float* ctx_out = g_ctx + (size_t)m * DMODEL + h * HDIM + d;

    if (focus) {                       // exact identity attention -> out = v
        *reinterpret_cast<float4*>(ctx_out) = v4;
        return;
    }

    // rotary: pairs (d,d+1) angle p0=d/2, (d+2,d+3) angle p1=d/2+1
    const float L2T = 0.41524101186092029f;   // log2(10000)/32
    float a0 = (float)n * exp2f(-(float)(d >> 1) * L2T);
    float a1 = (float)n * exp2f(-(float)((d >> 1) + 1) * L2T);
    float c0, s0, c1, s1;
    sincosf(a0, &s0, &c0);
    sincosf(a1, &s1, &c1);

    q4.x *= 0.125f; q4.y *= 0.125f; q4.z *= 0.125f; q4.w *= 0.125f;  // hd^-0.5

    float qx = q4.x * c0 - q4.y * s0, qy = q4.y * c0 + q4.x * s0;
    float qz = q4.z * c1 - q4.w * s1, qw = q4.w * c1 + q4.z * s1;
    float kx = k4.x * c0 - k4.y * s0, ky = k4.y * c0 + k4.x * s0;
    float kz = k4.z * c1 - k4.w * s1, kw = k4.w * c1 + k4.z * s1;

    *reinterpret_cast<float4*>(&qs[n][d]) = make_float4(qx, qy, qz, qw);
    *reinterpret_cast<float4*>(&ks[n][d]) = make_float4(kx, ky, kz, kw);
    *reinterpret_cast<float4*>(&vs[n][d]) = v4;
    __syncthreads();

    // sim[i][j] = q_i . k_j + pos_bias[h,i,j]  (thread (n,dg) -> (i=n, j=dg))
    {
        const float4* qr = reinterpret_cast<const float4*>(&qs[n][0]);
        const float4* kr = reinterpret_cast<const float4*>(&ks[dg][0]);
        float acc = 0.f;
#pragma unroll
        for (int dd = 0; dd < 16; dd++) {
            float4 a = qr[dd], bb = kr[dd];
            acc += a.x * bb.x + a.y * bb.y + a.z * bb.z + a.w * bb.w;
        }
        sim[n][dg] = acc + pos_bias[(h * 16 + n) * 16 + dg];
    }
    __syncthreads();

    // softmax per row (16 rows, one thread each)
    if (t < 16) {
        float mx = -FLT_MAX;
#pragma unroll
        for (int j = 0; j < 16; j++) mx = fmaxf(mx, sim[t][j]);
        float e[16], sum = 0.f;
#pragma unroll
        for (int j = 0; j < 16; j++) { e[j] = expf(sim[t][j] - mx); sum += e[j]; }
#pragma unroll
        for (int j = 0; j < 16; j++) sim[t][j] = e[j] / sum;
    }
    __syncthreads();

    // out[n][d..d+3] = sum_j attn[n][j] * v[j][d..d+3]
    float4 o = make_float4(0.f, 0.f, 0.f, 0.f);
#pragma unroll
    for (int j = 0; j < 16; j++) {
        float a = sim[n][j];
        float4 vv = *reinterpret_cast<const float4*>(&vs[j][d]);
        o.x = fmaf(a, vv.x, o.x); o.y = fmaf(a, vv.y, o.y);
        o.z = fmaf(a, vv.z, o.z); o.w = fmaf(a, vv.w, o.w);
    }
    *reinterpret_cast<float4*>(ctx_out) = o;
}

// ---------------------------------------------------------------------------
extern "C" void kernel_launch(void* const* d_in, const int* in_sizes, int n_in,
                              void* d_out, int out_size)
{
    const float* x     = (const float*)d_in[0];   // (4,1024,16,512)
    const float* pbias = (const float*)d_in[1];   // (8,16,16)
    const float* Wqkv  = (const float*)d_in[2];   // (512,1536)
    const float* Wout  = (const float*)d_in[3];   // (512,512)
    const unsigned char* fmask = (const unsigned char*)d_in[4];
    float* out = (float*)d_out;                   // (4,1024,16,512)

    float *qkv = nullptr, *ctx = nullptr;
    cudaGetSymbolAddress((void**)&qkv, g_qkv);
    cudaGetSymbolAddress((void**)&ctx, g_ctx);

    dim3 blk(256);

    // K1: qkv = x @ W_qkv   (65536 x 1536, K=512)
    dim3 g1(QKV_COLS / 128, M_ROWS / 128);
    sgemm128<<<g1, blk>>>(x, Wqkv, qkv, M_ROWS, QKV_COLS, DMODEL);

    // K2: fused rotary/attention -> g_ctx (65536 x 512)
    attn_kernel<<<B_SZ * S_LEN * NH, blk>>>(pbias, fmask);

    // K3: out = ctx @ W_out  (65536 x 512, K=512)
    dim3 g3(DMODEL / 128, M_ROWS / 128);
    sgemm128<<<g3, blk>>>(ctx, Wout, out, M_ROWS, DMODEL, DMODEL);
}

// round 9
// speedup vs baseline: 1.0008x; 1.0007x over previous
#include <cuda_runtime.h>
#include <cstdint>
#include <cfloat>

// Problem constants
#define B_SZ   4
#define S_LEN  1024
#define NTOK   16
#define DMODEL 512
#define NH     8
#define HDIM   64
#define M_ROWS (B_SZ * S_LEN * NTOK)   // 65536
#define QKV_COLS (3 * NH * HDIM)       // 1536

// Scratch (allocation-free rule: __device__ globals)
__device__ float g_qkv[(size_t)M_ROWS * QKV_COLS];   // 402 MB
__device__ float g_ctx[(size_t)M_ROWS * DMODEL];     // 128 MB

// ---------------------------------------------------------------------------
// K1/K3: classic 128x128x16 fp32 SGEMM, 256 threads, 8x8 per thread,
// float4 global loads, split 4+4 register tiles for conflict-free LDS.128.
// Dims are guaranteed multiples of tile sizes for this problem (no bounds).
// ---------------------------------------------------------------------------
__global__ __launch_bounds__(256) void sgemm128(
    const float* __restrict__ A, const float* __restrict__ B,
    float* __restrict__ C, int M, int N, int K)
{
    constexpr int BM = 128, BN = 128, BK = 16;
    __shared__ float As[BK][BM];
    __shared__ float Bs[BK][BN];

    const int tid  = threadIdx.x;
    const int tx   = tid & 15;
    const int ty   = tid >> 4;
    const int row0 = blockIdx.y * BM;
    const int col0 = blockIdx.x * BN;

    // global->smem load assignments
    const int a_r = tid >> 2;          // 0..63 (two passes: +0, +64)
    const int a_c = (tid & 3) << 2;    // 0,4,8,12
    const int b_r = tid >> 5;          // 0..7  (two passes: +0, +8)
    const int b_c = (tid & 31) << 2;   // 0..124

    const float* Ag = A + (size_t)row0 * K;
    const float* Bg = B + col0;

    float acc[8][8];
#pragma unroll
    for (int i = 0; i < 8; i++)
#pragma unroll
        for (int j = 0; j < 8; j++) acc[i][j] = 0.f;

    for (int k0 = 0; k0 < K; k0 += BK) {
#pragma unroll
        for (int i = 0; i < 2; i++) {
            int r = a_r + i * 64;
            float4 v = *reinterpret_cast<const float4*>(Ag + (size_t)r * K + k0 + a_c);
            As[a_c + 0][r] = v.x; As[a_c + 1][r] = v.y;
            As[a_c + 2][r] = v.z; As[a_c + 3][r] = v.w;
        }
#pragma unroll
        for (int i = 0; i < 2; i++) {
            int r = b_r + i * 8;
            *reinterpret_cast<float4*>(&Bs[r][b_c]) =
                *reinterpret_cast<const float4*>(Bg + (size_t)(k0 + r) * N + b_c);
        }
        __syncthreads();

#pragma unroll
        for (int kk = 0; kk < BK; kk++) {
            float ra[8], rb[8];
            *reinterpret_cast<float4*>(&ra[0]) = *reinterpret_cast<const float4*>(&As[kk][ty * 4]);
            *reinterpret_cast<float4*>(&ra[4]) = *reinterpret_cast<const float4*>(&As[kk][64 + ty * 4]);
            *reinterpret_cast<float4*>(&rb[0]) = *reinterpret_cast<const float4*>(&Bs[kk][tx * 4]);
            *reinterpret_cast<float4*>(&rb[4]) = *reinterpret_cast<const float4*>(&Bs[kk][64 + tx * 4]);
#pragma unroll
            for (int i = 0; i < 8; i++)
#pragma unroll
                for (int j = 0; j < 8; j++)
                    acc[i][j] = fmaf(ra[i], rb[j], acc[i][j]);
        }
        __syncthreads();
    }

#pragma unroll
    for (int ig = 0; ig < 2; ig++)
#pragma unroll
        for (int i = 0; i < 4; i++) {
            int r = row0 + ig * 64 + ty * 4 + i;
#pragma unroll
            for (int jg = 0; jg < 2; jg++) {
                int c = col0 + jg * 64 + tx * 4;
                float4 v = make_float4(acc[ig * 4 + i][jg * 4 + 0], acc[ig * 4 + i][jg * 4 + 1],
                                       acc[ig * 4 + i][jg * 4 + 2], acc[ig * 4 + i][jg * 4 + 3]);
                *reinterpret_cast<float4*>(C + (size_t)r * N + c) = v;
            }
        }
}

// ---------------------------------------------------------------------------
// K2: fused rotary + scale + sim + bias + mask + softmax + AV.
// One block per (b, s, h): 256 threads, thread t -> (n = t/16, dg = t%16).
// For focus batches, attention is exactly identity (one-hot softmax), so
// output = V bitwise; just copy.
// ---------------------------------------------------------------------------
__global__ __launch_bounds__(256) void attn_kernel(
    const float* __restrict__ pos_bias,
    const unsigned char* __restrict__ fmask)
{
    const int bs = blockIdx.x >> 3;     // b*S + s
    const int h  = blockIdx.x & 7;
    const int b  = bs / S_LEN;
    const int t  = threadIdx.x;
    const int n  = t >> 4;
    const int dg = t & 15;
    const int d  = dg << 2;

    __shared__ float qs[16][68];
    __shared__ float ks[16][68];
    __shared__ float vs[16][68];
    __shared__ float sim[16][17];

    // --- robust focus_present_mask read (bool may be u8 / i32 / f32) ---
    const uint32_t* fw = reinterpret_cast<const uint32_t*>(fmask);
    uint32_t w0 = fw[0], w1 = fw[1], w2 = fw[2], w3 = fw[3];
    bool is_f32 = ((w0 == 0u || w0 == 0x3F800000u) && (w1 == 0u || w1 == 0x3F800000u) &&
                   (w2 == 0u || w2 == 0x3F800000u) && (w3 == 0u || w3 == 0x3F800000u));
    bool is_i32 = ((w0 <= 1u) && (w1 <= 1u) && (w2 <= 1u) && (w3 <= 1u));
    bool focus;
    if (is_f32 || is_i32) {
        uint32_t wb = (b == 0) ? w0 : (b == 1) ? w1 : (b == 2) ? w2 : w3;
        focus = (wb != 0u);
    } else {
        focus = (fmask[b] != 0);
    }

    const int m = bs * NTOK + n;
    const float* row = g_qkv + (size_t)m * QKV_COLS + h * HDIM + d;
    float4 q4 = *reinterpret_cast<const float4*>(row);
    float4 k4 = *reinterpret_cast<const float4*>(row + 512);
    float4 v4 = *reinterpret_cast<const float4*>(row + 1024);

    float* ctx_out = g_ctx + (size_t)m * DMODEL + h * HDIM + d;

    if (focus) {                       // exact identity attention -> out = v
        *reinterpret_cast<float4*>(ctx_out) = v4;
        return;
    }

    // rotary: pairs (d,d+1) angle p0=d/2, (d+2,d+3) angle p1=d/2+1
    const float L2T = 0.41524101186092029f;   // log2(10000)/32
    float a0 = (float)n * exp2f(-(float)(d >> 1) * L2T);
    float a1 = (float)n * exp2f(-(float)((d >> 1) + 1) * L2T);
    float c0, s0, c1, s1;
    sincosf(a0, &s0, &c0);
    sincosf(a1, &s1, &c1);

    q4.x *= 0.125f; q4.y *= 0.125f; q4.z *= 0.125f; q4.w *= 0.125f;  // hd^-0.5

    float qx = q4.x * c0 - q4.y * s0, qy = q4.y * c0 + q4.x * s0;
    float qz = q4.z * c1 - q4.w * s1, qw = q4.w * c1 + q4.z * s1;
    float kx = k4.x * c0 - k4.y * s0, ky = k4.y * c0 + k4.x * s0;
    float kz = k4.z * c1 - k4.w * s1, kw = k4.w * c1 + k4.z * s1;

    *reinterpret_cast<float4*>(&qs[n][d]) = make_float4(qx, qy, qz, qw);
    *reinterpret_cast<float4*>(&ks[n][d]) = make_float4(kx, ky, kz, kw);
    *reinterpret_cast<float4*>(&vs[n][d]) = v4;
    __syncthreads();

    // sim[i][j] = q_i . k_j + pos_bias[h,i,j]  (thread (n,dg) -> (i=n, j=dg))
    {
        const float4* qr = reinterpret_cast<const float4*>(&qs[n][0]);
        const float4* kr = reinterpret_cast<const float4*>(&ks[dg][0]);
        float acc = 0.f;
#pragma unroll
        for (int dd = 0; dd < 16; dd++) {
            float4 a = qr[dd], bb = kr[dd];
            acc += a.x * bb.x + a.y * bb.y + a.z * bb.z + a.w * bb.w;
        }
        sim[n][dg] = acc + pos_bias[(h * 16 + n) * 16 + dg];
    }
    __syncthreads();

    // softmax per row (16 rows, one thread each)
    if (t < 16) {
        float mx = -FLT_MAX;
#pragma unroll
        for (int j = 0; j < 16; j++) mx = fmaxf(mx, sim[t][j]);
        float e[16], sum = 0.f;
#pragma unroll
        for (int j = 0; j < 16; j++) { e[j] = expf(sim[t][j] - mx); sum += e[j]; }
#pragma unroll
        for (int j = 0; j < 16; j++) sim[t][j] = e[j] / sum;
    }
    __syncthreads();

    // out[n][d..d+3] = sum_j attn[n][j] * v[j][d..d+3]
    float4 o = make_float4(0.f, 0.f, 0.f, 0.f);
#pragma unroll
    for (int j = 0; j < 16; j++) {
        float a = sim[n][j];
        float4 vv = *reinterpret_cast<const float4*>(&vs[j][d]);
        o.x = fmaf(a, vv.x, o.x); o.y = fmaf(a, vv.y, o.y);
        o.z = fmaf(a, vv.z, o.z); o.w = fmaf(a, vv.w, o.w);
    }
    *reinterpret_cast<float4*>(ctx_out) = o;
}

// ---------------------------------------------------------------------------
extern "C" void kernel_launch(void* const* d_in, const int* in_sizes, int n_in,
                              void* d_out, int out_size)
{
    const float* x     = (const float*)d_in[0];   // (4,1024,16,512)
    const float* pbias = (const float*)d_in[1];   // (8,16,16)
    const float* Wqkv  = (const float*)d_in[2];   // (512,1536)
    const float* Wout  = (const float*)d_in[3];   // (512,512)
    const unsigned char* fmask = (const unsigned char*)d_in[4];
    float* out = (float*)d_out;                   // (4,1024,16,512)

    float *qkv = nullptr, *ctx = nullptr;
    cudaGetSymbolAddress((void**)&qkv, g_qkv);
    cudaGetSymbolAddress((void**)&ctx, g_ctx);

    dim3 blk(256);

    // K1: qkv = x @ W_qkv   (65536 x 1536, K=512)
    dim3 g1(QKV_COLS / 128, M_ROWS / 128);
    sgemm128<<<g1, blk>>>(x, Wqkv, qkv, M_ROWS, QKV_COLS, DMODEL);

    // K2: fused rotary/attention -> g_ctx (65536 x 512)
    attn_kernel<<<B_SZ * S_LEN * NH, blk>>>(pbias, fmask);

    // K3: out = ctx @ W_out  (65536 x 512, K=512)
    dim3 g3(DMODEL / 128, M_ROWS / 128);
    sgemm128<<<g3, blk>>>(ctx, Wout, out, M_ROWS, DMODEL, DMODEL);
}

// round 10
// speedup vs baseline: 1.5484x; 1.5472x over previous
#include <cuda_runtime.h>
#include <cstdint>
#include <cfloat>

// Problem constants
#define B_SZ   4
#define S_LEN  1024
#define NTOK   16
#define DMODEL 512
#define NH     8
#define HDIM   64
#define M_ROWS (B_SZ * S_LEN * NTOK)   // 65536
#define QKV_COLS (3 * NH * HDIM)       // 1536

// Scratch (allocation-free rule: __device__ globals)
__device__ float g_qkv[(size_t)M_ROWS * QKV_COLS];   // 402 MB (focus rows left unwritten/unused)
__device__ float g_ctx[(size_t)M_ROWS * DMODEL];     // 128 MB (non-focus rows only)
__device__ float g_wcomb[DMODEL * DMODEL];           // 1 MB: Wqkv_V @ Wout
__device__ int   g_focus[B_SZ];

// ---------------------------------------------------------------------------
// Mask decode (bool may arrive as u8 / i32 / f32) -> g_focus
// ---------------------------------------------------------------------------
__global__ void decode_mask(const unsigned char* __restrict__ fmask)
{
    const uint32_t* fw = reinterpret_cast<const uint32_t*>(fmask);
    uint32_t w[4] = {fw[0], fw[1], fw[2], fw[3]};
    bool is_f32 = true, is_i32 = true;
#pragma unroll
    for (int i = 0; i < 4; i++) {
        is_f32 &= (w[i] == 0u || w[i] == 0x3F800000u);
        is_i32 &= (w[i] <= 1u);
    }
#pragma unroll
    for (int b = 0; b < 4; b++)
        g_focus[b] = (is_f32 || is_i32) ? (w[b] != 0u) : (fmask[b] != 0);
}

// ---------------------------------------------------------------------------
// Small 64x64x16 SGEMM for Wcomb = Wqkv[:,1024:] @ Wout (512x512x512).
// 64 blocks -> one wave across the chip. A has row stride lda.
// ---------------------------------------------------------------------------
__global__ __launch_bounds__(256) void sgemm64(
    const float* __restrict__ A, int lda,
    const float* __restrict__ B,
    float* __restrict__ C, int N, int K)
{
    constexpr int BM = 64, BN = 64, BK = 16;
    __shared__ float As[BK][68];
    __shared__ float Bs[BK][68];

    const int tid = threadIdx.x;
    const int tx = tid & 15, ty = tid >> 4;
    const int row0 = blockIdx.y * BM, col0 = blockIdx.x * BN;
    const int a_r = tid >> 2, a_c = (tid & 3) << 2;
    const int b_r = tid >> 4, b_c = (tid & 15) << 2;

    float acc[4][4];
#pragma unroll
    for (int i = 0; i < 4; i++)
#pragma unroll
        for (int j = 0; j < 4; j++) acc[i][j] = 0.f;

    for (int k0 = 0; k0 < K; k0 += BK) {
        float4 va = *reinterpret_cast<const float4*>(A + (size_t)(row0 + a_r) * lda + k0 + a_c);
        As[a_c + 0][a_r] = va.x; As[a_c + 1][a_r] = va.y;
        As[a_c + 2][a_r] = va.z; As[a_c + 3][a_r] = va.w;
        *reinterpret_cast<float4*>(&Bs[b_r][b_c]) =
            *reinterpret_cast<const float4*>(B + (size_t)(k0 + b_r) * N + col0 + b_c);
        __syncthreads();
#pragma unroll
        for (int kk = 0; kk < BK; kk++) {
            float4 ra = *reinterpret_cast<const float4*>(&As[kk][ty * 4]);
            float4 rb = *reinterpret_cast<const float4*>(&Bs[kk][tx * 4]);
            float a4[4] = {ra.x, ra.y, ra.z, ra.w};
            float b4[4] = {rb.x, rb.y, rb.z, rb.w};
#pragma unroll
            for (int i = 0; i < 4; i++)
#pragma unroll
                for (int j = 0; j < 4; j++)
                    acc[i][j] = fmaf(a4[i], b4[j], acc[i][j]);
        }
        __syncthreads();
    }
#pragma unroll
    for (int i = 0; i < 4; i++) {
        int r = row0 + ty * 4 + i;
        *reinterpret_cast<float4*>(C + (size_t)r * N + col0 + tx * 4) =
            make_float4(acc[i][0], acc[i][1], acc[i][2], acc[i][3]);
    }
}

// ---------------------------------------------------------------------------
// Main 128x128x16 SGEMM, double-buffered smem (one barrier per K-tile),
// padded smem rows (132) to reduce A-transpose STS conflicts.
// mode 0: plain.  mode 1: skip whole row-block if its batch is focus.
// mode 2: focus row-blocks use (A2, B2) instead of (A, B).
// A row stride == K, B/C row stride == N (holds for all call sites here).
// ---------------------------------------------------------------------------
__global__ __launch_bounds__(256, 2) void sgemm_db(
    const float* __restrict__ A, const float* __restrict__ B,
    const float* __restrict__ A2, const float* __restrict__ B2,
    float* __restrict__ C, int N, int K, int mode)
{
    constexpr int BM = 128, BN = 128, BK = 16, LDT = 132;
    __shared__ float As[2][BK][LDT];
    __shared__ float Bs[2][BK][LDT];

    const int row0 = blockIdx.y * BM;
    if (mode != 0) {
        const int focus = g_focus[row0 >> 14];   // 16384 rows per batch
        if (focus) {
            if (mode == 1) return;
            A = A2; B = B2;
        }
    }

    const int tid = threadIdx.x;
    const int tx = tid & 15, ty = tid >> 4;
    const int col0 = blockIdx.x * BN;

    const int a_r = tid >> 2;          // 0..63 (+0, +64)
    const int a_c = (tid & 3) << 2;    // 0,4,8,12
    const int b_r = tid >> 5;          // 0..7  (+0, +8)
    const int b_c = (tid & 31) << 2;   // 0..124

    const float* Ag = A + (size_t)row0 * K;
    const float* Bg = B + col0;

    float acc[8][8];
#pragma unroll
    for (int i = 0; i < 8; i++)
#pragma unroll
        for (int j = 0; j < 8; j++) acc[i][j] = 0.f;

    float4 pa[2], pb[2];
#pragma unroll
    for (int i = 0; i < 2; i++)
        pa[i] = *reinterpret_cast<const float4*>(Ag + (size_t)(a_r + i * 64) * K + a_c);
#pragma unroll
    for (int i = 0; i < 2; i++)
        pb[i] = *reinterpret_cast<const float4*>(Bg + (size_t)(b_r + i * 8) * N + b_c);

#pragma unroll
    for (int i = 0; i < 2; i++) {
        int r = a_r + i * 64;
        As[0][a_c + 0][r] = pa[i].x; As[0][a_c + 1][r] = pa[i].y;
        As[0][a_c + 2][r] = pa[i].z; As[0][a_c + 3][r] = pa[i].w;
    }
#pragma unroll
    for (int i = 0; i < 2; i++)
        *reinterpret_cast<float4*>(&Bs[0][b_r + i * 8][b_c]) = pb[i];
    __syncthreads();

    const int nt = K / BK;
    int cur = 0;
    for (int t = 0; t < nt; t++) {
        if (t + 1 < nt) {                 // issue next tile's LDGs before the FFMA block
            int k0 = (t + 1) * BK;
#pragma unroll
            for (int i = 0; i < 2; i++)
                pa[i] = *reinterpret_cast<const float4*>(Ag + (size_t)(a_r + i * 64) * K + k0 + a_c);
#pragma unroll
            for (int i = 0; i < 2; i++)
                pb[i] = *reinterpret_cast<const float4*>(Bg + (size_t)(k0 + b_r + i * 8) * N + b_c);
        }
#pragma unroll
        for (int kk = 0; kk < BK; kk++) {
            float ra[8], rb[8];
            *reinterpret_cast<float4*>(&ra[0]) = *reinterpret_cast<const float4*>(&As[cur][kk][ty * 4]);
            *reinterpret_cast<float4*>(&ra[4]) = *reinterpret_cast<const float4*>(&As[cur][kk][64 + ty * 4]);
            *reinterpret_cast<float4*>(&rb[0]) = *reinterpret_cast<const float4*>(&Bs[cur][kk][tx * 4]);
            *reinterpret_cast<float4*>(&rb[4]) = *reinterpret_cast<const float4*>(&Bs[cur][kk][64 + tx * 4]);
#pragma unroll
            for (int i = 0; i < 8; i++)
#pragma unroll
                for (int j = 0; j < 8; j++)
                    acc[i][j] = fmaf(ra[i], rb[j], acc[i][j]);
        }
        if (t + 1 < nt) {
            int nxt = cur ^ 1;
#pragma unroll
            for (int i = 0; i < 2; i++) {
                int r = a_r + i * 64;
                As[nxt][a_c + 0][r] = pa[i].x; As[nxt][a_c + 1][r] = pa[i].y;
                As[nxt][a_c + 2][r] = pa[i].z; As[nxt][a_c + 3][r] = pa[i].w;
            }
#pragma unroll
            for (int i = 0; i < 2; i++)
                *reinterpret_cast<float4*>(&Bs[nxt][b_r + i * 8][b_c]) = pb[i];
            __syncthreads();
            cur = nxt;
        }
    }

#pragma unroll
    for (int ig = 0; ig < 2; ig++)
#pragma unroll
        for (int i = 0; i < 4; i++) {
            int r = row0 + ig * 64 + ty * 4 + i;
#pragma unroll
            for (int jg = 0; jg < 2; jg++) {
                int c = col0 + jg * 64 + tx * 4;
                *reinterpret_cast<float4*>(C + (size_t)r * N + c) =
                    make_float4(acc[ig * 4 + i][jg * 4 + 0], acc[ig * 4 + i][jg * 4 + 1],
                                acc[ig * 4 + i][jg * 4 + 2], acc[ig * 4 + i][jg * 4 + 3]);
            }
        }
}

// ---------------------------------------------------------------------------
// Fused rotary + scale + sim + bias + softmax + AV. One block per (b,s,h).
// Focus batches are handled entirely by the composed-weight GEMM; skip them.
// ---------------------------------------------------------------------------
__global__ __launch_bounds__(256) void attn_kernel(const float* __restrict__ pos_bias)
{
    const int bs = blockIdx.x >> 3;     // b*S + s
    const int h  = blockIdx.x & 7;
    const int b  = bs / S_LEN;
    if (g_focus[b]) return;             // out = x @ Wcomb computed elsewhere

    const int t  = threadIdx.x;
    const int n  = t >> 4;
    const int dg = t & 15;
    const int d  = dg << 2;

    __shared__ float qs[16][68];
    __shared__ float ks[16][68];
    __shared__ float vs[16][68];
    __shared__ float sim[16][17];

    const int m = bs * NTOK + n;
    const float* row = g_qkv + (size_t)m * QKV_COLS + h * HDIM + d;
    float4 q4 = *reinterpret_cast<const float4*>(row);
    float4 k4 = *reinterpret_cast<const float4*>(row + 512);
    float4 v4 = *reinterpret_cast<const float4*>(row + 1024);

    // rotary: pairs (d,d+1) angle p0=d/2, (d+2,d+3) angle p1=d/2+1
    const float L2T = 0.41524101186092029f;   // log2(10000)/32
    float a0 = (float)n * exp2f(-(float)(d >> 1) * L2T);
    float a1 = (float)n * exp2f(-(float)((d >> 1) + 1) * L2T);
    float c0, s0, c1, s1;
    sincosf(a0, &s0, &c0);
    sincosf(a1, &s1, &c1);

    q4.x *= 0.125f; q4.y *= 0.125f; q4.z *= 0.125f; q4.w *= 0.125f;  // hd^-0.5

    float qx = q4.x * c0 - q4.y * s0, qy = q4.y * c0 + q4.x * s0;
    float qz = q4.z * c1 - q4.w * s1, qw = q4.w * c1 + q4.z * s1;
    float kx = k4.x * c0 - k4.y * s0, ky = k4.y * c0 + k4.x * s0;
    float kz = k4.z * c1 - k4.w * s1, kw = k4.w * c1 + k4.z * s1;

    *reinterpret_cast<float4*>(&qs[n][d]) = make_float4(qx, qy, qz, qw);
    *reinterpret_cast<float4*>(&ks[n][d]) = make_float4(kx, ky, kz, kw);
    *reinterpret_cast<float4*>(&vs[n][d]) = v4;
    __syncthreads();

    // sim[i][j] = q_i . k_j + pos_bias[h,i,j]
    {
        const float4* qr = reinterpret_cast<const float4*>(&qs[n][0]);
        const float4* kr = reinterpret_cast<const float4*>(&ks[dg][0]);
        float acc = 0.f;
#pragma unroll
        for (int dd = 0; dd < 16; dd++) {
            float4 a = qr[dd], bb = kr[dd];
            acc += a.x * bb.x + a.y * bb.y + a.z * bb.z + a.w * bb.w;
        }
        sim[n][dg] = acc + pos_bias[(h * 16 + n) * 16 + dg];
    }
    __syncthreads();

    if (t < 16) {
        float mx = -FLT_MAX;
#pragma unroll
        for (int j = 0; j < 16; j++) mx = fmaxf(mx, sim[t][j]);
        float e[16], sum = 0.f;
#pragma unroll
        for (int j = 0; j < 16; j++) { e[j] = expf(sim[t][j] - mx); sum += e[j]; }
#pragma unroll
        for (int j = 0; j < 16; j++) sim[t][j] = e[j] / sum;
    }
    __syncthreads();

    float4 o = make_float4(0.f, 0.f, 0.f, 0.f);
#pragma unroll
    for (int j = 0; j < 16; j++) {
        float a = sim[n][j];
        float4 vv = *reinterpret_cast<const float4*>(&vs[j][d]);
        o.x = fmaf(a, vv.x, o.x); o.y = fmaf(a, vv.y, o.y);
        o.z = fmaf(a, vv.z, o.z); o.w = fmaf(a, vv.w, o.w);
    }
    *reinterpret_cast<float4*>(g_ctx + (size_t)m * DMODEL + h * HDIM + d) = o;
}

// ---------------------------------------------------------------------------
extern "C" void kernel_launch(void* const* d_in, const int* in_sizes, int n_in,
                              void* d_out, int out_size)
{
    const float* x     = (const float*)d_in[0];   // (4,1024,16,512)
    const float* pbias = (const float*)d_in[1];   // (8,16,16)
    const float* Wqkv  = (const float*)d_in[2];   // (512,1536)
    const float* Wout  = (const float*)d_in[3];   // (512,512)
    const unsigned char* fmask = (const unsigned char*)d_in[4];
    float* out = (float*)d_out;                   // (4,1024,16,512)

    float *qkv = nullptr, *ctx = nullptr, *wcomb = nullptr;
    cudaGetSymbolAddress((void**)&qkv, g_qkv);
    cudaGetSymbolAddress((void**)&ctx, g_ctx);
    cudaGetSymbolAddress((void**)&wcomb, g_wcomb);

    dim3 blk(256);

    // 0) decode focus mask
    decode_mask<<<1, 1>>>(fmask);

    // 1) Wcomb = Wqkv[:,1024:1536] @ Wout   (512x512x512, one wave of 64 blocks)
    sgemm64<<<dim3(8, 8), blk>>>(Wqkv + 1024, QKV_COLS, Wout, wcomb, DMODEL, DMODEL);

    // 2) qkv = x @ W_qkv, skipping focus row-blocks entirely (mode 1)
    sgemm_db<<<dim3(QKV_COLS / 128, M_ROWS / 128), blk>>>(
        x, Wqkv, nullptr, nullptr, qkv, QKV_COLS, DMODEL, 1);

    // 3) fused attention -> g_ctx (non-focus rows only)
    attn_kernel<<<B_SZ * S_LEN * NH, blk>>>(pbias);

    // 4) out: non-focus = ctx @ Wout, focus = x @ Wcomb (mode 2)
    sgemm_db<<<dim3(DMODEL / 128, M_ROWS / 128), blk>>>(
        ctx, Wout, x, wcomb, out, DMODEL, DMODEL, 2);
}

// round 11
// speedup vs baseline: 1.5494x; 1.0006x over previous
#include <cuda_runtime.h>
#include <cstdint>
#include <cfloat>

// Problem constants
#define B_SZ   4
#define S_LEN  1024
#define NTOK   16
#define DMODEL 512
#define NH     8
#define HDIM   64
#define M_ROWS (B_SZ * S_LEN * NTOK)   // 65536
#define QKV_COLS (3 * NH * HDIM)       // 1536

// Scratch (allocation-free rule: __device__ globals)
__device__ float g_qkv[(size_t)M_ROWS * QKV_COLS];   // 402 MB (focus rows left unwritten/unused)
__device__ float g_ctx[(size_t)M_ROWS * DMODEL];     // 128 MB (non-focus rows only)
__device__ float g_wcomb[DMODEL * DMODEL];           // 1 MB: Wqkv_V @ Wout
__device__ int   g_focus[B_SZ];

// ---------------------------------------------------------------------------
// Mask decode (bool may arrive as u8 / i32 / f32) -> g_focus
// ---------------------------------------------------------------------------
__global__ void decode_mask(const unsigned char* __restrict__ fmask)
{
    const uint32_t* fw = reinterpret_cast<const uint32_t*>(fmask);
    uint32_t w[4] = {fw[0], fw[1], fw[2], fw[3]};
    bool is_f32 = true, is_i32 = true;
#pragma unroll
    for (int i = 0; i < 4; i++) {
        is_f32 &= (w[i] == 0u || w[i] == 0x3F800000u);
        is_i32 &= (w[i] <= 1u);
    }
#pragma unroll
    for (int b = 0; b < 4; b++)
        g_focus[b] = (is_f32 || is_i32) ? (w[b] != 0u) : (fmask[b] != 0);
}

// ---------------------------------------------------------------------------
// Small 64x64x16 SGEMM for Wcomb = Wqkv[:,1024:] @ Wout (512x512x512).
// 64 blocks -> one wave across the chip. A has row stride lda.
// ---------------------------------------------------------------------------
__global__ __launch_bounds__(256) void sgemm64(
    const float* __restrict__ A, int lda,
    const float* __restrict__ B,
    float* __restrict__ C, int N, int K)
{
    constexpr int BM = 64, BN = 64, BK = 16;
    __shared__ float As[BK][68];
    __shared__ float Bs[BK][68];

    const int tid = threadIdx.x;
    const int tx = tid & 15, ty = tid >> 4;
    const int row0 = blockIdx.y * BM, col0 = blockIdx.x * BN;
    const int a_r = tid >> 2, a_c = (tid & 3) << 2;
    const int b_r = tid >> 4, b_c = (tid & 15) << 2;

    float acc[4][4];
#pragma unroll
    for (int i = 0; i < 4; i++)
#pragma unroll
        for (int j = 0; j < 4; j++) acc[i][j] = 0.f;

    for (int k0 = 0; k0 < K; k0 += BK) {
        float4 va = *reinterpret_cast<const float4*>(A + (size_t)(row0 + a_r) * lda + k0 + a_c);
        As[a_c + 0][a_r] = va.x; As[a_c + 1][a_r] = va.y;
        As[a_c + 2][a_r] = va.z; As[a_c + 3][a_r] = va.w;
        *reinterpret_cast<float4*>(&Bs[b_r][b_c]) =
            *reinterpret_cast<const float4*>(B + (size_t)(k0 + b_r) * N + col0 + b_c);
        __syncthreads();
#pragma unroll
        for (int kk = 0; kk < BK; kk++) {
            float4 ra = *reinterpret_cast<const float4*>(&As[kk][ty * 4]);
            float4 rb = *reinterpret_cast<const float4*>(&Bs[kk][tx * 4]);
            float a4[4] = {ra.x, ra.y, ra.z, ra.w};
            float b4[4] = {rb.x, rb.y, rb.z, rb.w};
#pragma unroll
            for (int i = 0; i < 4; i++)
#pragma unroll
                for (int j = 0; j < 4; j++)
                    acc[i][j] = fmaf(a4[i], b4[j], acc[i][j]);
        }
        __syncthreads();
    }
#pragma unroll
    for (int i = 0; i < 4; i++) {
        int r = row0 + ty * 4 + i;
        *reinterpret_cast<float4*>(C + (size_t)r * N + col0 + tx * 4) =
            make_float4(acc[i][0], acc[i][1], acc[i][2], acc[i][3]);
    }
}

// ---------------------------------------------------------------------------
// Main 128x128x16 SGEMM, double-buffered smem (one barrier per K-tile),
// padded smem rows (132) to reduce A-transpose STS conflicts.
// mode 0: plain.  mode 1: skip whole row-block if its batch is focus.
// mode 2: focus row-blocks use (A2, B2) instead of (A, B).
// A row stride == K, B/C row stride == N (holds for all call sites here).
// ---------------------------------------------------------------------------
__global__ __launch_bounds__(256, 2) void sgemm_db(
    const float* __restrict__ A, const float* __restrict__ B,
    const float* __restrict__ A2, const float* __restrict__ B2,
    float* __restrict__ C, int N, int K, int mode)
{
    constexpr int BM = 128, BN = 128, BK = 16, LDT = 132;
    __shared__ float As[2][BK][LDT];
    __shared__ float Bs[2][BK][LDT];

    const int row0 = blockIdx.y * BM;
    if (mode != 0) {
        const int focus = g_focus[row0 >> 14];   // 16384 rows per batch
        if (focus) {
            if (mode == 1) return;
            A = A2; B = B2;
        }
    }

    const int tid = threadIdx.x;
    const int tx = tid & 15, ty = tid >> 4;
    const int col0 = blockIdx.x * BN;

    const int a_r = tid >> 2;          // 0..63 (+0, +64)
    const int a_c = (tid & 3) << 2;    // 0,4,8,12
    const int b_r = tid >> 5;          // 0..7  (+0, +8)
    const int b_c = (tid & 31) << 2;   // 0..124

    const float* Ag = A + (size_t)row0 * K;
    const float* Bg = B + col0;

    float acc[8][8];
#pragma unroll
    for (int i = 0; i < 8; i++)
#pragma unroll
        for (int j = 0; j < 8; j++) acc[i][j] = 0.f;

    float4 pa[2], pb[2];
#pragma unroll
    for (int i = 0; i < 2; i++)
        pa[i] = *reinterpret_cast<const float4*>(Ag + (size_t)(a_r + i * 64) * K + a_c);
#pragma unroll
    for (int i = 0; i < 2; i++)
        pb[i] = *reinterpret_cast<const float4*>(Bg + (size_t)(b_r + i * 8) * N + b_c);

#pragma unroll
    for (int i = 0; i < 2; i++) {
        int r = a_r + i * 64;
        As[0][a_c + 0][r] = pa[i].x; As[0][a_c + 1][r] = pa[i].y;
        As[0][a_c + 2][r] = pa[i].z; As[0][a_c + 3][r] = pa[i].w;
    }
#pragma unroll
    for (int i = 0; i < 2; i++)
        *reinterpret_cast<float4*>(&Bs[0][b_r + i * 8][b_c]) = pb[i];
    __syncthreads();

    const int nt = K / BK;
    int cur = 0;
    for (int t = 0; t < nt; t++) {
        if (t + 1 < nt) {                 // issue next tile's LDGs before the FFMA block
            int k0 = (t + 1) * BK;
#pragma unroll
            for (int i = 0; i < 2; i++)
                pa[i] = *reinterpret_cast<const float4*>(Ag + (size_t)(a_r + i * 64) * K + k0 + a_c);
#pragma unroll
            for (int i = 0; i < 2; i++)
                pb[i] = *reinterpret_cast<const float4*>(Bg + (size_t)(k0 + b_r + i * 8) * N + b_c);
        }
#pragma unroll
        for (int kk = 0; kk < BK; kk++) {
            float ra[8], rb[8];
            *reinterpret_cast<float4*>(&ra[0]) = *reinterpret_cast<const float4*>(&As[cur][kk][ty * 4]);
            *reinterpret_cast<float4*>(&ra[4]) = *reinterpret_cast<const float4*>(&As[cur][kk][64 + ty * 4]);
            *reinterpret_cast<float4*>(&rb[0]) = *reinterpret_cast<const float4*>(&Bs[cur][kk][tx * 4]);
            *reinterpret_cast<float4*>(&rb[4]) = *reinterpret_cast<const float4*>(&Bs[cur][kk][64 + tx * 4]);
#pragma unroll
            for (int i = 0; i < 8; i++)
#pragma unroll
                for (int j = 0; j < 8; j++)
                    acc[i][j] = fmaf(ra[i], rb[j], acc[i][j]);
        }
        if (t + 1 < nt) {
            int nxt = cur ^ 1;
#pragma unroll
            for (int i = 0; i < 2; i++) {
                int r = a_r + i * 64;
                As[nxt][a_c + 0][r] = pa[i].x; As[nxt][a_c + 1][r] = pa[i].y;
                As[nxt][a_c + 2][r] = pa[i].z; As[nxt][a_c + 3][r] = pa[i].w;
            }
#pragma unroll
            for (int i = 0; i < 2; i++)
                *reinterpret_cast<float4*>(&Bs[nxt][b_r + i * 8][b_c]) = pb[i];
            __syncthreads();
            cur = nxt;
        }
    }

#pragma unroll
    for (int ig = 0; ig < 2; ig++)
#pragma unroll
        for (int i = 0; i < 4; i++) {
            int r = row0 + ig * 64 + ty * 4 + i;
#pragma unroll
            for (int jg = 0; jg < 2; jg++) {
                int c = col0 + jg * 64 + tx * 4;
                *reinterpret_cast<float4*>(C + (size_t)r * N + c) =
                    make_float4(acc[ig * 4 + i][jg * 4 + 0], acc[ig * 4 + i][jg * 4 + 1],
                                acc[ig * 4 + i][jg * 4 + 2], acc[ig * 4 + i][jg * 4 + 3]);
            }
        }
}

// ---------------------------------------------------------------------------
// Fused rotary + scale + sim + bias + softmax + AV. One block per (b,s,h).
// Focus batches are handled entirely by the composed-weight GEMM; skip them.
// ---------------------------------------------------------------------------
__global__ __launch_bounds__(256) void attn_kernel(const float* __restrict__ pos_bias)
{
    const int bs = blockIdx.x >> 3;     // b*S + s
    const int h  = blockIdx.x & 7;
    const int b  = bs / S_LEN;
    if (g_focus[b]) return;             // out = x @ Wcomb computed elsewhere

    const int t  = threadIdx.x;
    const int n  = t >> 4;
    const int dg = t & 15;
    const int d  = dg << 2;

    __shared__ float qs[16][68];
    __shared__ float ks[16][68];
    __shared__ float vs[16][68];
    __shared__ float sim[16][17];

    const int m = bs * NTOK + n;
    const float* row = g_qkv + (size_t)m * QKV_COLS + h * HDIM + d;
    float4 q4 = *reinterpret_cast<const float4*>(row);
    float4 k4 = *reinterpret_cast<const float4*>(row + 512);
    float4 v4 = *reinterpret_cast<const float4*>(row + 1024);

    // rotary: pairs (d,d+1) angle p0=d/2, (d+2,d+3) angle p1=d/2+1
    const float L2T = 0.41524101186092029f;   // log2(10000)/32
    float a0 = (float)n * exp2f(-(float)(d >> 1) * L2T);
    float a1 = (float)n * exp2f(-(float)((d >> 1) + 1) * L2T);
    float c0, s0, c1, s1;
    sincosf(a0, &s0, &c0);
    sincosf(a1, &s1, &c1);

    q4.x *= 0.125f; q4.y *= 0.125f; q4.z *= 0.125f; q4.w *= 0.125f;  // hd^-0.5

    float qx = q4.x * c0 - q4.y * s0, qy = q4.y * c0 + q4.x * s0;
    float qz = q4.z * c1 - q4.w * s1, qw = q4.w * c1 + q4.z * s1;
    float kx = k4.x * c0 - k4.y * s0, ky = k4.y * c0 + k4.x * s0;
    float kz = k4.z * c1 - k4.w * s1, kw = k4.w * c1 + k4.z * s1;

    *reinterpret_cast<float4*>(&qs[n][d]) = make_float4(qx, qy, qz, qw);
    *reinterpret_cast<float4*>(&ks[n][d]) = make_float4(kx, ky, kz, kw);
    *reinterpret_cast<float4*>(&vs[n][d]) = v4;
    __syncthreads();

    // sim[i][j] = q_i . k_j + pos_bias[h,i,j]
    {
        const float4* qr = reinterpret_cast<const float4*>(&qs[n][0]);
        const float4* kr = reinterpret_cast<const float4*>(&ks[dg][0]);
        float acc = 0.f;
#pragma unroll
        for (int dd = 0; dd < 16; dd++) {
            float4 a = qr[dd], bb = kr[dd];
            acc += a.x * bb.x + a.y * bb.y + a.z * bb.z + a.w * bb.w;
        }
        sim[n][dg] = acc + pos_bias[(h * 16 + n) * 16 + dg];
    }
    __syncthreads();

    if (t < 16) {
        float mx = -FLT_MAX;
#pragma unroll
        for (int j = 0; j < 16; j++) mx = fmaxf(mx, sim[t][j]);
        float e[16], sum = 0.f;
#pragma unroll
        for (int j = 0; j < 16; j++) { e[j] = expf(sim[t][j] - mx); sum += e[j]; }
#pragma unroll
        for (int j = 0; j < 16; j++) sim[t][j] = e[j] / sum;
    }
    __syncthreads();

    float4 o = make_float4(0.f, 0.f, 0.f, 0.f);
#pragma unroll
    for (int j = 0; j < 16; j++) {
        float a = sim[n][j];
        float4 vv = *reinterpret_cast<const float4*>(&vs[j][d]);
        o.x = fmaf(a, vv.x, o.x); o.y = fmaf(a, vv.y, o.y);
        o.z = fmaf(a, vv.z, o.z); o.w = fmaf(a, vv.w, o.w);
    }
    *reinterpret_cast<float4*>(g_ctx + (size_t)m * DMODEL + h * HDIM + d) = o;
}

// ---------------------------------------------------------------------------
extern "C" void kernel_launch(void* const* d_in, const int* in_sizes, int n_in,
                              void* d_out, int out_size)
{
    const float* x     = (const float*)d_in[0];   // (4,1024,16,512)
    const float* pbias = (const float*)d_in[1];   // (8,16,16)
    const float* Wqkv  = (const float*)d_in[2];   // (512,1536)
    const float* Wout  = (const float*)d_in[3];   // (512,512)
    const unsigned char* fmask = (const unsigned char*)d_in[4];
    float* out = (float*)d_out;                   // (4,1024,16,512)

    float *qkv = nullptr, *ctx = nullptr, *wcomb = nullptr;
    cudaGetSymbolAddress((void**)&qkv, g_qkv);
    cudaGetSymbolAddress((void**)&ctx, g_ctx);
    cudaGetSymbolAddress((void**)&wcomb, g_wcomb);

    dim3 blk(256);

    // 0) decode focus mask
    decode_mask<<<1, 1>>>(fmask);

    // 1) Wcomb = Wqkv[:,1024:1536] @ Wout   (512x512x512, one wave of 64 blocks)
    sgemm64<<<dim3(8, 8), blk>>>(Wqkv + 1024, QKV_COLS, Wout, wcomb, DMODEL, DMODEL);

    // 2) qkv = x @ W_qkv, skipping focus row-blocks entirely (mode 1)
    sgemm_db<<<dim3(QKV_COLS / 128, M_ROWS / 128), blk>>>(
        x, Wqkv, nullptr, nullptr, qkv, QKV_COLS, DMODEL, 1);

    // 3) fused attention -> g_ctx (non-focus rows only)
    attn_kernel<<<B_SZ * S_LEN * NH, blk>>>(pbias);

    // 4) out: non-focus = ctx @ Wout, focus = x @ Wcomb (mode 2)
    sgemm_db<<<dim3(DMODEL / 128, M_ROWS / 128), blk>>>(
        ctx, Wout, x, wcomb, out, DMODEL, DMODEL, 2);
}

// round 12
// speedup vs baseline: 1.5515x; 1.0014x over previous
#include <cuda_runtime.h>
#include <cstdint>
#include <cfloat>

// Problem constants
#define B_SZ   4
#define S_LEN  1024
#define NTOK   16
#define DMODEL 512
#define NH     8
#define HDIM   64
#define M_ROWS (B_SZ * S_LEN * NTOK)   // 65536
#define QKV_COLS (3 * NH * HDIM)       // 1536

// Scratch (allocation-free rule: __device__ globals)
__device__ float g_qkv[(size_t)M_ROWS * QKV_COLS];   // 402 MB (focus rows left unwritten/unused)
__device__ float g_ctx[(size_t)M_ROWS * DMODEL];     // 128 MB (non-focus rows only)
__device__ float g_wcomb[DMODEL * DMODEL];           // 1 MB: Wqkv_V @ Wout
__device__ int   g_focus[B_SZ];

// ---------------------------------------------------------------------------
// Mask decode (bool may arrive as u8 / i32 / f32) -> g_focus
// ---------------------------------------------------------------------------
__global__ void decode_mask(const unsigned char* __restrict__ fmask)
{
    const uint32_t* fw = reinterpret_cast<const uint32_t*>(fmask);
    uint32_t w[4] = {fw[0], fw[1], fw[2], fw[3]};
    bool is_f32 = true, is_i32 = true;
#pragma unroll
    for (int i = 0; i < 4; i++) {
        is_f32 &= (w[i] == 0u || w[i] == 0x3F800000u);
        is_i32 &= (w[i] <= 1u);
    }
#pragma unroll
    for (int b = 0; b < 4; b++)
        g_focus[b] = (is_f32 || is_i32) ? (w[b] != 0u) : (fmask[b] != 0);
}

// ---------------------------------------------------------------------------
// Small 64x64x16 SGEMM for Wcomb = Wqkv[:,1024:] @ Wout (512x512x512).
// 64 blocks -> one wave across the chip. A has row stride lda.
// ---------------------------------------------------------------------------
__global__ __launch_bounds__(256) void sgemm64(
    const float* __restrict__ A, int lda,
    const float* __restrict__ B,
    float* __restrict__ C, int N, int K)
{
    constexpr int BM = 64, BN = 64, BK = 16;
    __shared__ float As[BK][68];
    __shared__ float Bs[BK][68];

    const int tid = threadIdx.x;
    const int tx = tid & 15, ty = tid >> 4;
    const int row0 = blockIdx.y * BM, col0 = blockIdx.x * BN;
    const int a_r = tid >> 2, a_c = (tid & 3) << 2;
    const int b_r = tid >> 4, b_c = (tid & 15) << 2;

    float acc[4][4];
#pragma unroll
    for (int i = 0; i < 4; i++)
#pragma unroll
        for (int j = 0; j < 4; j++) acc[i][j] = 0.f;

    for (int k0 = 0; k0 < K; k0 += BK) {
        float4 va = *reinterpret_cast<const float4*>(A + (size_t)(row0 + a_r) * lda + k0 + a_c);
        As[a_c + 0][a_r] = va.x; As[a_c + 1][a_r] = va.y;
        As[a_c + 2][a_r] = va.z; As[a_c + 3][a_r] = va.w;
        *reinterpret_cast<float4*>(&Bs[b_r][b_c]) =
            *reinterpret_cast<const float4*>(B + (size_t)(k0 + b_r) * N + col0 + b_c);
        __syncthreads();
#pragma unroll
        for (int kk = 0; kk < BK; kk++) {
            float4 ra = *reinterpret_cast<const float4*>(&As[kk][ty * 4]);
            float4 rb = *reinterpret_cast<const float4*>(&Bs[kk][tx * 4]);
            float a4[4] = {ra.x, ra.y, ra.z, ra.w};
            float b4[4] = {rb.x, rb.y, rb.z, rb.w};
#pragma unroll
            for (int i = 0; i < 4; i++)
#pragma unroll
                for (int j = 0; j < 4; j++)
                    acc[i][j] = fmaf(a4[i], b4[j], acc[i][j]);
        }
        __syncthreads();
    }
#pragma unroll
    for (int i = 0; i < 4; i++) {
        int r = row0 + ty * 4 + i;
        *reinterpret_cast<float4*>(C + (size_t)r * N + col0 + tx * 4) =
            make_float4(acc[i][0], acc[i][1], acc[i][2], acc[i][3]);
    }
}

// ---------------------------------------------------------------------------
// Main 128x128x16 SGEMM, double-buffered smem (one barrier per K-tile),
// padded smem rows (132) to reduce A-transpose STS conflicts.
// mode 0: plain.  mode 1: skip whole row-block if its batch is focus.
// mode 2: focus row-blocks use (A2, B2) instead of (A, B).
// A row stride == K, B/C row stride == N (holds for all call sites here).
// ---------------------------------------------------------------------------
__global__ __launch_bounds__(256, 2) void sgemm_db(
    const float* __restrict__ A, const float* __restrict__ B,
    const float* __restrict__ A2, const float* __restrict__ B2,
    float* __restrict__ C, int N, int K, int mode)
{
    constexpr int BM = 128, BN = 128, BK = 16, LDT = 132;
    __shared__ float As[2][BK][LDT];
    __shared__ float Bs[2][BK][LDT];

    const int row0 = blockIdx.y * BM;
    if (mode != 0) {
        const int focus = g_focus[row0 >> 14];   // 16384 rows per batch
        if (focus) {
            if (mode == 1) return;
            A = A2; B = B2;
        }
    }

    const int tid = threadIdx.x;
    const int tx = tid & 15, ty = tid >> 4;
    const int col0 = blockIdx.x * BN;

    const int a_r = tid >> 2;          // 0..63 (+0, +64)
    const int a_c = (tid & 3) << 2;    // 0,4,8,12
    const int b_r = tid >> 5;          // 0..7  (+0, +8)
    const int b_c = (tid & 31) << 2;   // 0..124

    const float* Ag = A + (size_t)row0 * K;
    const float* Bg = B + col0;

    float acc[8][8];
#pragma unroll
    for (int i = 0; i < 8; i++)
#pragma unroll
        for (int j = 0; j < 8; j++) acc[i][j] = 0.f;

    float4 pa[2], pb[2];
#pragma unroll
    for (int i = 0; i < 2; i++)
        pa[i] = *reinterpret_cast<const float4*>(Ag + (size_t)(a_r + i * 64) * K + a_c);
#pragma unroll
    for (int i = 0; i < 2; i++)
        pb[i] = *reinterpret_cast<const float4*>(Bg + (size_t)(b_r + i * 8) * N + b_c);

#pragma unroll
    for (int i = 0; i < 2; i++) {
        int r = a_r + i * 64;
        As[0][a_c + 0][r] = pa[i].x; As[0][a_c + 1][r] = pa[i].y;
        As[0][a_c + 2][r] = pa[i].z; As[0][a_c + 3][r] = pa[i].w;
    }
#pragma unroll
    for (int i = 0; i < 2; i++)
        *reinterpret_cast<float4*>(&Bs[0][b_r + i * 8][b_c]) = pb[i];
    __syncthreads();

    const int nt = K / BK;
    int cur = 0;
    for (int t = 0; t < nt; t++) {
        if (t + 1 < nt) {                 // issue next tile's LDGs before the FFMA block
            int k0 = (t + 1) * BK;
#pragma unroll
            for (int i = 0; i < 2; i++)
                pa[i] = *reinterpret_cast<const float4*>(Ag + (size_t)(a_r + i * 64) * K + k0 + a_c);
#pragma unroll
            for (int i = 0; i < 2; i++)
                pb[i] = *reinterpret_cast<const float4*>(Bg + (size_t)(k0 + b_r + i * 8) * N + b_c);
        }
#pragma unroll
        for (int kk = 0; kk < BK; kk++) {
            float ra[8], rb[8];
            *reinterpret_cast<float4*>(&ra[0]) = *reinterpret_cast<const float4*>(&As[cur][kk][ty * 4]);
            *reinterpret_cast<float4*>(&ra[4]) = *reinterpret_cast<const float4*>(&As[cur][kk][64 + ty * 4]);
            *reinterpret_cast<float4*>(&rb[0]) = *reinterpret_cast<const float4*>(&Bs[cur][kk][tx * 4]);
            *reinterpret_cast<float4*>(&rb[4]) = *reinterpret_cast<const float4*>(&Bs[cur][kk][64 + tx * 4]);
#pragma unroll
            for (int i = 0; i < 8; i++)
#pragma unroll
                for (int j = 0; j < 8; j++)
                    acc[i][j] = fmaf(ra[i], rb[j], acc[i][j]);
        }
        if (t + 1 < nt) {
            int nxt = cur ^ 1;
#pragma unroll
            for (int i = 0; i < 2; i++) {
                int r = a_r + i * 64;
                As[nxt][a_c + 0][r] = pa[i].x; As[nxt][a_c + 1][r] = pa[i].y;
                As[nxt][a_c + 2][r] = pa[i].z; As[nxt][a_c + 3][r] = pa[i].w;
            }
#pragma unroll
            for (int i = 0; i < 2; i++)
                *reinterpret_cast<float4*>(&Bs[nxt][b_r + i * 8][b_c]) = pb[i];
            __syncthreads();
            cur = nxt;
        }
    }

#pragma unroll
    for (int ig = 0; ig < 2; ig++)
#pragma unroll
        for (int i = 0; i < 4; i++) {
            int r = row0 + ig * 64 + ty * 4 + i;
#pragma unroll
            for (int jg = 0; jg < 2; jg++) {
                int c = col0 + jg * 64 + tx * 4;
                *reinterpret_cast<float4*>(C + (size_t)r * N + c) =
                    make_float4(acc[ig * 4 + i][jg * 4 + 0], acc[ig * 4 + i][jg * 4 + 1],
                                acc[ig * 4 + i][jg * 4 + 2], acc[ig * 4 + i][jg * 4 + 3]);
            }
        }
}

// ---------------------------------------------------------------------------
// Fused rotary + scale + sim + bias + softmax + AV. One block per (b,s,h).
// Focus batches are handled entirely by the composed-weight GEMM; skip them.
// ---------------------------------------------------------------------------
__global__ __launch_bounds__(256) void attn_kernel(const float* __restrict__ pos_bias)
{
    const int bs = blockIdx.x >> 3;     // b*S + s
    const int h  = blockIdx.x & 7;
    const int b  = bs / S_LEN;
    if (g_focus[b]) return;             // out = x @ Wcomb computed elsewhere

    const int t  = threadIdx.x;
    const int n  = t >> 4;
    const int dg = t & 15;
    const int d  = dg << 2;

    __shared__ float qs[16][68];
    __shared__ float ks[16][68];
    __shared__ float vs[16][68];
    __shared__ float sim[16][17];

    const int m = bs * NTOK + n;
    const float* row = g_qkv + (size_t)m * QKV_COLS + h * HDIM + d;
    float4 q4 = *reinterpret_cast<const float4*>(row);
    float4 k4 = *reinterpret_cast<const float4*>(row + 512);
    float4 v4 = *reinterpret_cast<const float4*>(row + 1024);

    // rotary: pairs (d,d+1) angle p0=d/2, (d+2,d+3) angle p1=d/2+1
    const float L2T = 0.41524101186092029f;   // log2(10000)/32
    float a0 = (float)n * exp2f(-(float)(d >> 1) * L2T);
    float a1 = (float)n * exp2f(-(float)((d >> 1) + 1) * L2T);
    float c0, s0, c1, s1;
    sincosf(a0, &s0, &c0);
    sincosf(a1, &s1, &c1);

    q4.x *= 0.125f; q4.y *= 0.125f; q4.z *= 0.125f; q4.w *= 0.125f;  // hd^-0.5

    float qx = q4.x * c0 - q4.y * s0, qy = q4.y * c0 + q4.x * s0;
    float qz = q4.z * c1 - q4.w * s1, qw = q4.w * c1 + q4.z * s1;
    float kx = k4.x * c0 - k4.y * s0, ky = k4.y * c0 + k4.x * s0;
    float kz = k4.z * c1 - k4.w * s1, kw = k4.w * c1 + k4.z * s1;

    *reinterpret_cast<float4*>(&qs[n][d]) = make_float4(qx, qy, qz, qw);
    *reinterpret_cast<float4*>(&ks[n][d]) = make_float4(kx, ky, kz, kw);
    *reinterpret_cast<float4*>(&vs[n][d]) = v4;
    __syncthreads();

    // sim[i][j] = q_i . k_j + pos_bias[h,i,j]
    {
        const float4* qr = reinterpret_cast<const float4*>(&qs[n][0]);
        const float4* kr = reinterpret_cast<const float4*>(&ks[dg][0]);
        float acc = 0.f;
#pragma unroll
        for (int dd = 0; dd < 16; dd++) {
            float4 a = qr[dd], bb = kr[dd];
            acc += a.x * bb.x + a.y * bb.y + a.z * bb.z + a.w * bb.w;
        }
        sim[n][dg] = acc + pos_bias[(h * 16 + n) * 16 + dg];
    }
    __syncthreads();

    if (t < 16) {
        float mx = -FLT_MAX;
#pragma unroll
        for (int j = 0; j < 16; j++) mx = fmaxf(mx, sim[t][j]);
        float e[16], sum = 0.f;
#pragma unroll
        for (int j = 0; j < 16; j++) { e[j] = expf(sim[t][j] - mx); sum += e[j]; }
#pragma unroll
        for (int j = 0; j < 16; j++) sim[t][j] = e[j] / sum;
    }
    __syncthreads();

    float4 o = make_float4(0.f, 0.f, 0.f, 0.f);
#pragma unroll
    for (int j = 0; j < 16; j++) {
        float a = sim[n][j];
        float4 vv = *reinterpret_cast<const float4*>(&vs[j][d]);
        o.x = fmaf(a, vv.x, o.x); o.y = fmaf(a, vv.y, o.y);
        o.z = fmaf(a, vv.z, o.z); o.w = fmaf(a, vv.w, o.w);
    }
    *reinterpret_cast<float4*>(g_ctx + (size_t)m * DMODEL + h * HDIM + d) = o;
}

// ---------------------------------------------------------------------------
extern "C" void kernel_launch(void* const* d_in, const int* in_sizes, int n_in,
                              void* d_out, int out_size)
{
    const float* x     = (const float*)d_in[0];   // (4,1024,16,512)
    const float* pbias = (const float*)d_in[1];   // (8,16,16)
    const float* Wqkv  = (const float*)d_in[2];   // (512,1536)
    const float* Wout  = (const float*)d_in[3];   // (512,512)
    const unsigned char* fmask = (const unsigned char*)d_in[4];
    float* out = (float*)d_out;                   // (4,1024,16,512)

    float *qkv = nullptr, *ctx = nullptr, *wcomb = nullptr;
    cudaGetSymbolAddress((void**)&qkv, g_qkv);
    cudaGetSymbolAddress((void**)&ctx, g_ctx);
    cudaGetSymbolAddress((void**)&wcomb, g_wcomb);

    dim3 blk(256);

    // 0) decode focus mask
    decode_mask<<<1, 1>>>(fmask);

    // 1) Wcomb = Wqkv[:,1024:1536] @ Wout   (512x512x512, one wave of 64 blocks)
    sgemm64<<<dim3(8, 8), blk>>>(Wqkv + 1024, QKV_COLS, Wout, wcomb, DMODEL, DMODEL);

    // 2) qkv = x @ W_qkv, skipping focus row-blocks entirely (mode 1)
    sgemm_db<<<dim3(QKV_COLS / 128, M_ROWS / 128), blk>>>(
        x, Wqkv, nullptr, nullptr, qkv, QKV_COLS, DMODEL, 1);

    // 3) fused attention -> g_ctx (non-focus rows only)
    attn_kernel<<<B_SZ * S_LEN * NH, blk>>>(pbias);

    // 4) out: non-focus = ctx @ Wout, focus = x @ Wcomb (mode 2)
    sgemm_db<<<dim3(DMODEL / 128, M_ROWS / 128), blk>>>(
        ctx, Wout, x, wcomb, out, DMODEL, DMODEL, 2);
}